// round 3
// baseline (speedup 1.0000x reference)
#include <cuda_runtime.h>
#include <cuda_fp16.h>
#include <cstdint>
#include <cstddef>

// Problem constants
#define BATCH   65536
#define MTILE   64
#define TILES   (BATCH / MTILE)       // 1024 work tiles
#define GRID    148                   // persistent: 1 CTA per SM
#define THREADS 512                   // 16 warps
#define VOFF    (BATCH * 16)          // value output offset (policy [B,16] first)

// h=c=0 at t=0  =>  Whh* unused, f-gate unused. Pack only gates {i,g,o} (src rows 0,2,3 *128).
// Packed row r in [0,384): gate = r>>7 (0->i,1->g,2->o), hidden j = r&127.

__device__ __align__(16) __half g_W0[384 * 64];    // [384][64]  fp16
__device__ __align__(16) __half g_W1[384 * 128];   // [384][128] fp16
__device__ __align__(16) __half g_Wh[24 * 128];    // rows 0-15 Wp, 16 Wv, 17-23 zero
__device__ float g_b0[384];                        // PRE-SCALED: -L2E*(bih+bhh) (i,o) / -2L2E*... (g)
__device__ float g_b1[384];
__device__ float g_bh[24];                         // bp, bv, zeros (raw)

#define L2E 1.4426950408889634f

__device__ __forceinline__ int gate_src(int gsel) { return gsel == 0 ? 0 : (gsel == 1 ? 2 : 3); }

// ---------------- prep: pack/convert weights ----------------
__global__ void prep_kernel(const float* __restrict__ Wih0, const float* __restrict__ bih0,
                            const float* __restrict__ bhh0, const float* __restrict__ Wih1,
                            const float* __restrict__ bih1, const float* __restrict__ bhh1,
                            const float* __restrict__ Wp,   const float* __restrict__ bp,
                            const float* __restrict__ Wv,   const float* __restrict__ bv) {
  int i = blockIdx.x * blockDim.x + threadIdx.x;
  if (i < 384 * 64)  { int r = i >> 6, k = i & 63;  int src = gate_src(r >> 7) * 128 + (r & 127);
                       g_W0[i] = __float2half(Wih0[src * 64 + k]);  return; }
  i -= 384 * 64;
  if (i < 384 * 128) { int r = i >> 7, k = i & 127; int src = gate_src(r >> 7) * 128 + (r & 127);
                       g_W1[i] = __float2half(Wih1[src * 128 + k]); return; }
  i -= 384 * 128;
  if (i < 24 * 128)  { int n = i >> 7, k = i & 127;
                       float v = (n < 16) ? Wp[n * 128 + k] : ((n == 16) ? Wv[k] : 0.0f);
                       g_Wh[i] = __float2half(v); return; }
  i -= 24 * 128;
  if (i < 384) { int gsel = i >> 7, src = gate_src(gsel) * 128 + (i & 127);
                 float sc = (gsel == 1) ? -2.0f * L2E : -L2E;
                 g_b0[i] = sc * (bih0[src] + bhh0[src]); return; }
  i -= 384;
  if (i < 384) { int gsel = i >> 7, src = gate_src(gsel) * 128 + (i & 127);
                 float sc = (gsel == 1) ? -2.0f * L2E : -L2E;
                 g_b1[i] = sc * (bih1[src] + bhh1[src]); return; }
  i -= 384;
  if (i < 24)  { g_bh[i] = (i < 16) ? bp[i] : ((i == 16) ? bv[0] : 0.0f); }
}

// ---------------- activation: 5 MUFU per cell ----------------
// h = sigmoid(o) * tanh( sigmoid(i) * tanh(g) )          (f-gate dead: c_prev = 0)
// ei = 2^(-L2E*i), eg = 2^(-2L2E*g), eo = 2^(-L2E*o)  [bias pre-folded into sb*, FFMA-imm rt1]
//   c  = (1-eg) * rcp((1+ei)(1+eg))                       (sigmoid(i)*tanh(g), exact)
//   tanh(c) = c(105+10u)/(105+45u+u^2), u=c^2             (Pade/CF depth-4, |err|<=5e-6 on |c|<1)
//   h  = c(105+10u) * rcp((105+45u+u^2)*(1+eo))           (Pade divide FUSED with sigmoid(o) rcp)
__device__ __forceinline__ float fex2(float v) { float y; asm("ex2.approx.f32 %0, %1;" : "=f"(y) : "f"(v)); return y; }
__device__ __forceinline__ float frcp(float v) { float y; asm("rcp.approx.f32 %0, %1;" : "=f"(y) : "f"(v)); return y; }
__device__ __forceinline__ float lstm_h(float aI, float aG, float aO, float sbI, float sbG, float sbO) {
  float ei = fex2(fmaf(aI, -L2E,        sbI));
  float eg = fex2(fmaf(aG, -2.0f * L2E, sbG));
  float eo = fex2(fmaf(aO, -L2E,        sbO));
  float c  = (1.0f - eg) * frcp((1.0f + ei) * (1.0f + eg));
  float u  = c * c;
  float nt = c * fmaf(u, 10.0f, 105.0f);
  float dt = fmaf(u + 45.0f, u, 105.0f);
  return nt * frcp(dt * (1.0f + eo));
}

// ---------------- mma / ldmatrix helpers ----------------
__device__ __forceinline__ uint32_t su32(const void* p) { return (uint32_t)__cvta_generic_to_shared(p); }
__device__ __forceinline__ void ldmx4(uint32_t& r0, uint32_t& r1, uint32_t& r2, uint32_t& r3, uint32_t a) {
  asm volatile("ldmatrix.sync.aligned.m8n8.x4.shared.b16 {%0,%1,%2,%3}, [%4];"
               : "=r"(r0), "=r"(r1), "=r"(r2), "=r"(r3) : "r"(a));
}
__device__ __forceinline__ void ldmx2(uint32_t& r0, uint32_t& r1, uint32_t a) {
  asm volatile("ldmatrix.sync.aligned.m8n8.x2.shared.b16 {%0,%1}, [%2];"
               : "=r"(r0), "=r"(r1) : "r"(a));
}
__device__ __forceinline__ void mma16816(float* c, uint32_t a0, uint32_t a1, uint32_t a2, uint32_t a3,
                                         uint32_t b0, uint32_t b1) {
  asm volatile("mma.sync.aligned.m16n8k16.row.col.f32.f16.f16.f32 "
               "{%0,%1,%2,%3}, {%4,%5,%6,%7}, {%8,%9}, {%0,%1,%2,%3};"
               : "+f"(c[0]), "+f"(c[1]), "+f"(c[2]), "+f"(c[3])
               : "r"(a0), "r"(a1), "r"(a2), "r"(a3), "r"(b0), "r"(b1));
}

// Smem layout (halfs). Row strides padded (+8) for conflict-free ldmatrix.
//   sW0 : 384 x 72   @ 0        (27648)
//   sW1 : 384 x 136  @ 27648    (52224)
//   sWh :  24 x 136  @ 79872    (3264)
//   xs  :  64 x 72   @ 83136    (4608)
//   h0s :  16 x 136  @ 87744    (2176)
//   h1s : 2 x 16x136 @ 89920    (4352)   total 94272 halfs = 188544 B
#define SMEM_BYTES 188544

__global__ void __launch_bounds__(THREADS, 1)
lstm_main(const float* __restrict__ x, float* __restrict__ out) {
  extern __shared__ __half smem[];
  __half* sW0 = smem;
  __half* sW1 = smem + 27648;
  __half* sWh = smem + 79872;
  __half* xs  = smem + 83136;
  __half* h0s = smem + 87744;
  __half* h1s = smem + 89920;

  const int tid  = threadIdx.x;
  const int warp = tid >> 5;
  const int lane = tid & 31;

  // ---- stage weights ONCE per persistent block (L2-hot across 148 blocks) ----
  for (int w = tid; w < 384 * 8;  w += THREADS) { int r = w >> 3, c = w & 7;
    ((uint4*)(sW0 + r * 72))[c]  = ((const uint4*)g_W0)[w]; }
  for (int w = tid; w < 384 * 16; w += THREADS) { int r = w >> 4, c = w & 15;
    ((uint4*)(sW1 + r * 136))[c] = ((const uint4*)g_W1)[w]; }
  for (int w = tid; w < 24 * 16;  w += THREADS) { int r = w >> 4, c = w & 15;
    ((uint4*)(sWh + r * 136))[c] = ((const uint4*)g_Wh)[w]; }

  // ---- stage x for first tile ----
  int t = blockIdx.x;   // GRID <= TILES always
  {
    const float4* xp = (const float4*)x + (size_t)t * MTILE * 16;
    float4 v = xp[tid];
    int r = tid >> 4, c = tid & 15;
    __half2* d = (__half2*)(xs + r * 72 + c * 4);
    d[0] = __floats2half2_rn(v.x, v.y); d[1] = __floats2half2_rn(v.z, v.w);
    float4 v2 = xp[tid + 512];
    __half2* d2 = (__half2*)(xs + (r + 32) * 72 + c * 4);
    d2[0] = __floats2half2_rn(v2.x, v2.y); d2[1] = __floats2half2_rn(v2.z, v2.w);
  }
  __syncthreads();

  // fragment lane geometry (mma.m16n8k16 canonical layouts)
  const int g    = lane >> 2, q = lane & 3;
  const int jw   = warp * 8;                      // this warp's 8 hidden columns
  const int lr8  = lane & 7;
  const int a_row = ((lane >> 3) & 1) * 8 + lr8;  // ldmatrix.x4 (A, row-major)
  const int a_col = ((lane >> 4) & 1) * 8;
  const int b_row = lr8;                          // ldmatrix.x2 (B, [n][k] rows)
  const int b_col = ((lane >> 3) & 1) * 8;
  const int cc0  = jw + 2 * q;

  // ---- hoist ALL layer-1 B fragments to registers (invariant; kills 24 ldmx2/warp/mt) ----
  uint32_t B1[3][8][2];
#pragma unroll
  for (int gg = 0; gg < 3; ++gg)
#pragma unroll
    for (int ks = 0; ks < 8; ++ks)
      ldmx2(B1[gg][ks][0], B1[gg][ks][1],
            su32(sW1 + (gg * 128 + jw + b_row) * 136 + ks * 16 + b_col));

  // hoist scaled biases
  const float bI0 = g_b0[cc0],       bI1 = g_b0[cc0 + 1];
  const float bG0 = g_b0[128 + cc0], bG1 = g_b0[128 + cc0 + 1];
  const float bO0 = g_b0[256 + cc0], bO1 = g_b0[256 + cc0 + 1];
  const float dI0 = g_b1[cc0],       dI1 = g_b1[cc0 + 1];
  const float dG0 = g_b1[128 + cc0], dG1 = g_b1[128 + cc0 + 1];
  const float dO0 = g_b1[256 + cc0], dO1 = g_b1[256 + cc0 + 1];
  float bh0 = 0.0f, bh1 = 0.0f;
  if (warp < 3) { bh0 = g_bh[warp * 8 + 2 * q]; bh1 = g_bh[warp * 8 + 2 * q + 1]; }

  while (true) {
    const int m0 = t * MTILE;
    const int tn = t + GRID;
    const bool pf = (tn < TILES);

    // prefetch next x tile into registers (hidden under ~20K cyc of compute)
    float4 xa, xb;
    if (pf) {
      const float4* xp = (const float4*)x + (size_t)tn * MTILE * 16;
      xa = xp[tid];
      xb = xp[tid + 512];
    }

#pragma unroll
    for (int mt = 0; mt < MTILE / 16; ++mt) {
      const int rb = mt * 16;
      __half* hb = h1s + (mt & 1) * 2176;   // double-buffered h1 tile

      // ===== layer 0 : gates = x @ W0p^T  (K=64) =====
      float aI[4] = {0, 0, 0, 0}, aG[4] = {0, 0, 0, 0}, aO[4] = {0, 0, 0, 0};
#pragma unroll
      for (int ks = 0; ks < 4; ++ks) {
        uint32_t A0, A1, A2, A3, B0, B1r;
        ldmx4(A0, A1, A2, A3, su32(xs + (rb + a_row) * 72 + ks * 16 + a_col));
        ldmx2(B0, B1r, su32(sW0 + (0 * 128 + jw + b_row) * 72 + ks * 16 + b_col));
        mma16816(aI, A0, A1, A2, A3, B0, B1r);
        ldmx2(B0, B1r, su32(sW0 + (1 * 128 + jw + b_row) * 72 + ks * 16 + b_col));
        mma16816(aG, A0, A1, A2, A3, B0, B1r);
        ldmx2(B0, B1r, su32(sW0 + (2 * 128 + jw + b_row) * 72 + ks * 16 + b_col));
        mma16816(aO, A0, A1, A2, A3, B0, B1r);
      }
      {
        float h00 = lstm_h(aI[0], aG[0], aO[0], bI0, bG0, bO0);
        float h01 = lstm_h(aI[1], aG[1], aO[1], bI1, bG1, bO1);
        float h10 = lstm_h(aI[2], aG[2], aO[2], bI0, bG0, bO0);
        float h11 = lstm_h(aI[3], aG[3], aO[3], bI1, bG1, bO1);
        *(__half2*)(h0s + g * 136 + cc0)       = __floats2half2_rn(h00, h01);
        *(__half2*)(h0s + (g + 8) * 136 + cc0) = __floats2half2_rn(h10, h11);
      }
      __syncthreads();   // h0s ready (also orders xs rewrite at tile end)

      // ===== layer 1 : gates = h0 @ W1p^T  (K=128, B in registers) =====
      float eI[4] = {0, 0, 0, 0}, eG[4] = {0, 0, 0, 0}, eO[4] = {0, 0, 0, 0};
#pragma unroll
      for (int ks = 0; ks < 8; ++ks) {
        uint32_t A0, A1, A2, A3;
        ldmx4(A0, A1, A2, A3, su32(h0s + a_row * 136 + ks * 16 + a_col));
        mma16816(eI, A0, A1, A2, A3, B1[0][ks][0], B1[0][ks][1]);
        mma16816(eG, A0, A1, A2, A3, B1[1][ks][0], B1[1][ks][1]);
        mma16816(eO, A0, A1, A2, A3, B1[2][ks][0], B1[2][ks][1]);
      }
      {
        float h00 = lstm_h(eI[0], eG[0], eO[0], dI0, dG0, dO0);
        float h01 = lstm_h(eI[1], eG[1], eO[1], dI1, dG1, dO1);
        float h10 = lstm_h(eI[2], eG[2], eO[2], dI0, dG0, dO0);
        float h11 = lstm_h(eI[3], eG[3], eO[3], dI1, dG1, dO1);
        *(__half2*)(hb + g * 136 + cc0)       = __floats2half2_rn(h00, h01);
        *(__half2*)(hb + (g + 8) * 136 + cc0) = __floats2half2_rn(h10, h11);
      }
      __syncthreads();   // hb ready; h0s reads done (safe to rewrite next mt)

      // ===== heads : [16x128] @ [128x24] (Wp rows 0-15, Wv row 16) =====
      // No trailing sync: next m-tile writes the OTHER h1 buffer; this buffer's
      // next write is two syncs away.
      if (warp < 3) {
        float p[4] = {0, 0, 0, 0};
#pragma unroll
        for (int ks = 0; ks < 8; ++ks) {
          uint32_t A0, A1, A2, A3, B0, B1r;
          ldmx4(A0, A1, A2, A3, su32(hb + a_row * 136 + ks * 16 + a_col));
          ldmx2(B0, B1r, su32(sWh + (warp * 8 + b_row) * 136 + ks * 16 + b_col));
          mma16816(p, A0, A1, A2, A3, B0, B1r);
        }
        const int n0 = warp * 8 + 2 * q;
        const int mA = m0 + rb + g, mB = mA + 8;
        if (warp < 2) {             // pure policy columns: vectorized STG.64
          float2 vA = make_float2(p[0] + bh0, p[1] + bh1);
          float2 vB = make_float2(p[2] + bh0, p[3] + bh1);
          *(float2*)(out + (size_t)mA * 16 + n0) = vA;
          *(float2*)(out + (size_t)mB * 16 + n0) = vB;
        } else if (q == 0) {        // n0 == 16: value head
          out[VOFF + mA] = p[0] + bh0;
          out[VOFF + mB] = p[2] + bh0;
        }                           // n 17..23: padding, discard
      }
    }

    if (!pf) break;

    // commit prefetched x (all xs reads are behind the post-L0 barrier of mt=3)
    {
      int r = tid >> 4, c = tid & 15;
      __half2* d = (__half2*)(xs + r * 72 + c * 4);
      d[0] = __floats2half2_rn(xa.x, xa.y); d[1] = __floats2half2_rn(xa.z, xa.w);
      __half2* d2 = (__half2*)(xs + (r + 32) * 72 + c * 4);
      d2[0] = __floats2half2_rn(xb.x, xb.y); d2[1] = __floats2half2_rn(xb.z, xb.w);
    }
    __syncthreads();
    t = tn;
  }
}

// ---------------- launch ----------------
extern "C" void kernel_launch(void* const* d_in, const int* in_sizes, int n_in,
                              void* d_out, int out_size) {
  const float* x    = (const float*)d_in[0];
  const float* Wih0 = (const float*)d_in[1];
  // d_in[2] = Whh0 : unused (h_init = 0)
  const float* bih0 = (const float*)d_in[3];
  const float* bhh0 = (const float*)d_in[4];
  const float* Wih1 = (const float*)d_in[5];
  // d_in[6] = Whh1 : unused
  const float* bih1 = (const float*)d_in[7];
  const float* bhh1 = (const float*)d_in[8];
  const float* Wp   = (const float*)d_in[9];
  const float* bp   = (const float*)d_in[10];
  const float* Wv   = (const float*)d_in[11];
  const float* bv   = (const float*)d_in[12];
  float* out = (float*)d_out;

  cudaFuncSetAttribute(lstm_main, cudaFuncAttributeMaxDynamicSharedMemorySize, SMEM_BYTES);

  const int prep_total = 384 * 64 + 384 * 128 + 24 * 128 + 384 + 384 + 24;  // 77592
  prep_kernel<<<(prep_total + 255) / 256, 256>>>(Wih0, bih0, bhh0, Wih1, bih1, bhh1, Wp, bp, Wv, bv);
  lstm_main<<<GRID, THREADS, SMEM_BYTES>>>(x, out);
}

// round 14
// speedup vs baseline: 1.0371x; 1.0371x over previous
#include <cuda_runtime.h>
#include <cuda_fp16.h>
#include <cstdint>
#include <cstddef>

// ---------------- problem constants ----------------
#define BATCH   65536
#define GRID    148
#define THREADS 512                    // 16 warps
#define NCHUNK  (BATCH / 16)           // 4096 chunks of 16 batch rows
#define WSLOTS  (GRID * 16)            // 2368 warp slots -> max 2 chunks/warp
#define VOFF    (BATCH * 16)           // value output offset
#define L2E 1.4426950408889634f

// h=c=0 at t=0 => Whh* unused, f-gate unused. Pack gates {i,g,o} (src rows 0,2,3 *128).
// Weights PRE-SCALED by -L2E (i,o) / -2L2E (g) so activation consumes ex2(gate) directly.
// Bias folded in as an extra k-column (k=64 for L0, k=128 for L1/heads) hit by a
// constant-1.0 A column -> no bias loads anywhere in the main loop.
//
// Global packed weights in EXACT smem layout (row strides padded for conflict-free ldmatrix):
//   g_W0 : 384 rows x 88 halfs  (k 0..63 = W, k64 = bias, rest 0)   33792 halfs
//   g_W1 : 384 rows x 152 halfs (k 0..127 = W, k128 = bias)          58368 halfs
//   g_Wh :  24 rows x 144 halfs (rows 0-15 Wp, 16 Wv; k128 = bias)    3456 halfs
__device__ __align__(16) __half g_W0[384 * 88];
__device__ __align__(16) __half g_W1[384 * 152];
__device__ __align__(16) __half g_Wh[24 * 144];

__device__ __forceinline__ int gate_src(int gsel) { return gsel == 0 ? 0 : (gsel == 1 ? 2 : 3); }

// ---------------- prep: pack/convert/scale weights ----------------
__global__ void prep_kernel(const float* __restrict__ Wih0, const float* __restrict__ bih0,
                            const float* __restrict__ bhh0, const float* __restrict__ Wih1,
                            const float* __restrict__ bih1, const float* __restrict__ bhh1,
                            const float* __restrict__ Wp,   const float* __restrict__ bp,
                            const float* __restrict__ Wv,   const float* __restrict__ bv) {
  int i = blockIdx.x * blockDim.x + threadIdx.x;
  if (i < 384 * 88) {
    int r = i / 88, k = i % 88;
    int gsel = r >> 7, src = gate_src(gsel) * 128 + (r & 127);
    float sc = (gsel == 1) ? -2.0f * L2E : -L2E;
    float v = 0.0f;
    if (k < 64)       v = sc * Wih0[src * 64 + k];
    else if (k == 64) v = sc * (bih0[src] + bhh0[src]);
    g_W0[i] = __float2half(v); return;
  }
  i -= 384 * 88;
  if (i < 384 * 152) {
    int r = i / 152, k = i % 152;
    int gsel = r >> 7, src = gate_src(gsel) * 128 + (r & 127);
    float sc = (gsel == 1) ? -2.0f * L2E : -L2E;
    float v = 0.0f;
    if (k < 128)       v = sc * Wih1[src * 128 + k];
    else if (k == 128) v = sc * (bih1[src] + bhh1[src]);
    g_W1[i] = __float2half(v); return;
  }
  i -= 384 * 152;
  if (i < 24 * 144) {
    int n = i / 144, k = i % 144;
    float v = 0.0f;
    if (n < 16)       { if (k < 128) v = Wp[n * 128 + k]; else if (k == 128) v = bp[n]; }
    else if (n == 16) { if (k < 128) v = Wv[k];           else if (k == 128) v = bv[0]; }
    g_Wh[i] = __float2half(v); return;
  }
}

// ---------------- activation: 4 MUFU + 16 FMA-ops / cell (balanced pipes) ----------------
// aI = -L2E*(i-gate), aG = -2L2E*(g-gate), aO = -L2E*(o-gate)   (bias included via GEMM)
// ei=2^aI=e^-i, eg=2^aG=e^-2g, eo=2^aO=e^-o
//   sigmoid(i)*tanh(g) = (1-eg)/((1+ei)(1+eg)) = A/B
//   tanh(c) = c(105+10u)/(105+45u+u^2), u=c^2   (|c|<1, |err|<=5e-6)
//   h = sigmoid(o)*tanh(A/B) = A*B*t * rcp( (s*(t+35r)+r^2)*(1+eo) )
//     where r=A^2, s=B^2, t=105s+10r   [105s+45r = t+35r; den poly = 105s^2+45rs+r^2]
// 3x ex2 + 1x rcp. Range audit: |gates|<2.5 -> B<~150, den<~3e12 << f32 max.
__device__ __forceinline__ float fex2(float v) { float y; asm("ex2.approx.f32 %0, %1;" : "=f"(y) : "f"(v)); return y; }
__device__ __forceinline__ float frcp(float v) { float y; asm("rcp.approx.f32 %0, %1;" : "=f"(y) : "f"(v)); return y; }
__device__ __forceinline__ float lstm_h(float aI, float aG, float aO) {
  float ei = fex2(aI);
  float eg = fex2(aG);
  float eo = fex2(aO);
  float A  = 1.0f - eg;
  float B  = (1.0f + ei) * (1.0f + eg);
  float r  = A * A, s = B * B;
  float t  = fmaf(s, 105.0f, 10.0f * r);          // 105s + 10r
  float num = (A * B) * t;
  float den = fmaf(s, fmaf(r, 35.0f, t), r * r) * (1.0f + eo);
  return num * frcp(den);
}

// ---------------- mma / ldmatrix helpers ----------------
__device__ __forceinline__ uint32_t su32(const void* p) { return (uint32_t)__cvta_generic_to_shared(p); }
__device__ __forceinline__ void ldmx4(uint32_t& r0, uint32_t& r1, uint32_t& r2, uint32_t& r3, uint32_t a) {
  asm volatile("ldmatrix.sync.aligned.m8n8.x4.shared.b16 {%0,%1,%2,%3}, [%4];"
               : "=r"(r0), "=r"(r1), "=r"(r2), "=r"(r3) : "r"(a));
}
__device__ __forceinline__ void ldmx2(uint32_t& r0, uint32_t& r1, uint32_t a) {
  asm volatile("ldmatrix.sync.aligned.m8n8.x2.shared.b16 {%0,%1}, [%2];"
               : "=r"(r0), "=r"(r1) : "r"(a));
}
__device__ __forceinline__ void mma16816(float* c, const uint32_t* a, uint32_t b0, uint32_t b1) {
  asm volatile("mma.sync.aligned.m16n8k16.row.col.f32.f16.f16.f32 "
               "{%0,%1,%2,%3}, {%4,%5,%6,%7}, {%8,%9}, {%0,%1,%2,%3};"
               : "+f"(c[0]), "+f"(c[1]), "+f"(c[2]), "+f"(c[3])
               : "r"(a[0]), "r"(a[1]), "r"(a[2]), "r"(a[3]), "r"(b0), "r"(b1));
}
__device__ __forceinline__ uint32_t pack2(float a, float b) {
  __half2 t = __floats2half2_rn(a, b); return *(uint32_t*)&t;
}

// Smem (halfs): sW0 [0,33792) | sW1 [33792,92160) | sWh [92160,95616) | xs [95616,116096)
// xs: per-warp private slice, 16 rows x 80 halfs (k64=1.0 bias col, 65..79=0)
#define SMEM_BYTES (116096 * 2)   // 232192 <= 232448 max

__global__ void __launch_bounds__(THREADS, 1)
lstm_main(const float* __restrict__ x, float* __restrict__ out) {
  extern __shared__ __half smem[];
  __half* sW0 = smem;
  __half* sW1 = smem + 33792;
  __half* sWh = smem + 92160;
  __half* xs  = smem + 95616;

  const int tid = threadIdx.x, warp = tid >> 5, lane = tid & 31;

  // ---- stage weights once (flat copies; layouts identical) ----
  for (int i = tid; i < 4224; i += THREADS) ((uint4*)sW0)[i] = ((const uint4*)g_W0)[i];
  for (int i = tid; i < 7296; i += THREADS) ((uint4*)sW1)[i] = ((const uint4*)g_W1)[i];
  for (int i = tid; i < 432;  i += THREADS) ((uint4*)sWh)[i] = ((const uint4*)g_Wh)[i];
  __syncthreads();   // ONLY block-wide sync in the kernel

  // lane geometry
  const int g = lane >> 2, q = lane & 3;
  const int a_row = ((lane >> 3) & 1) * 8 + (lane & 7);   // A ldmx4: row within 16
  const int a_col = ((lane >> 4) & 1) * 8;                // A ldmx4: k offset
  const int b4_row = ((lane >> 4) & 1) * 8 + (lane & 7);  // B ldmx4: n-row within 16
  const int b4_kof = ((lane >> 3) & 1) * 8;               // B ldmx4: k offset
  __half* myxs = xs + warp * 1280;

  // constant A fragment for the bias k-chunk: col 0 of chunk == 1.0
  uint32_t CA[4];
  CA[0] = (q == 0) ? 0x3C00u : 0u;  CA[1] = CA[0];  CA[2] = 0;  CA[3] = 0;

  for (int chunk = blockIdx.x * 16 + warp; chunk < NCHUNK; chunk += WSLOTS) {
    // ---- warp-private x staging: 16 rows x 64 f32 -> fp16 (+bias col), no block sync ----
    __syncwarp();
    const float4* xp = (const float4*)x + (size_t)chunk * 256;
#pragma unroll
    for (int i = 0; i < 8; ++i) {
      int f = i * 32 + lane;          // 0..255 float4s, coalesced
      float4 v = xp[f];
      int r = f >> 4, c4 = f & 15;
      uint2 w = make_uint2(pack2(v.x, v.y), pack2(v.z, v.w));
      *(uint2*)(myxs + r * 80 + c4 * 4) = w;
    }
    if (lane < 16) {
      *(uint4*)(myxs + lane * 80 + 64) = make_uint4(0x3C00u, 0, 0, 0);  // [1,0,...]
      *(uint4*)(myxs + lane * 80 + 72) = make_uint4(0, 0, 0, 0);
    }
    __syncwarp();

    // ---- x A-fragments (K=80 incl bias chunk): 5 x ldmx4 ----
    uint32_t xA[5][4];
#pragma unroll
    for (int kc = 0; kc < 5; ++kc)
      ldmx4(xA[kc][0], xA[kc][1], xA[kc][2], xA[kc][3],
            su32(myxs + a_row * 80 + kc * 16 + a_col));

    // ================= layer 0: gates for ALL 128 hidden cols, this warp's 16 rows =================
    uint32_t hA[9][4];                 // h0 as A-fragments (8 k-chunks + const bias chunk)
#pragma unroll
    for (int cb = 0; cb < 8; ++cb) {   // 16 hidden cols per iteration (2 n-tiles)
      float aI[8] = {0,0,0,0,0,0,0,0}, aG[8] = {0,0,0,0,0,0,0,0}, aO[8] = {0,0,0,0,0,0,0,0};
#pragma unroll
      for (int kc = 0; kc < 5; ++kc) {
        uint32_t b[4];
        ldmx4(b[0], b[1], b[2], b[3], su32(sW0 + (cb * 16 + b4_row) * 88 + kc * 16 + b4_kof));
        mma16816(aI,     xA[kc], b[0], b[1]);
        mma16816(aI + 4, xA[kc], b[2], b[3]);
        ldmx4(b[0], b[1], b[2], b[3], su32(sW0 + (128 + cb * 16 + b4_row) * 88 + kc * 16 + b4_kof));
        mma16816(aG,     xA[kc], b[0], b[1]);
        mma16816(aG + 4, xA[kc], b[2], b[3]);
        ldmx4(b[0], b[1], b[2], b[3], su32(sW0 + (256 + cb * 16 + b4_row) * 88 + kc * 16 + b4_kof));
        mma16816(aO,     xA[kc], b[0], b[1]);
        mma16816(aO + 4, xA[kc], b[2], b[3]);
      }
      float h0 = lstm_h(aI[0], aG[0], aO[0]);
      float h1 = lstm_h(aI[1], aG[1], aO[1]);
      float h2 = lstm_h(aI[2], aG[2], aO[2]);
      float h3 = lstm_h(aI[3], aG[3], aO[3]);
      float h4 = lstm_h(aI[4], aG[4], aO[4]);
      float h5 = lstm_h(aI[5], aG[5], aO[5]);
      float h6 = lstm_h(aI[6], aG[6], aO[6]);
      float h7 = lstm_h(aI[7], aG[7], aO[7]);
      // C-layout -> A-fragment of the next GEMM (register handoff, no smem)
      hA[cb][0] = pack2(h0, h1);  hA[cb][1] = pack2(h2, h3);
      hA[cb][2] = pack2(h4, h5);  hA[cb][3] = pack2(h6, h7);
    }
    hA[8][0] = CA[0]; hA[8][1] = CA[1]; hA[8][2] = CA[2]; hA[8][3] = CA[3];

    // ================= layer 1: K=128 (+bias chunk) =================
    uint32_t h1A[9][4];
#pragma unroll
    for (int cb = 0; cb < 8; ++cb) {
      float aI[8] = {0,0,0,0,0,0,0,0}, aG[8] = {0,0,0,0,0,0,0,0}, aO[8] = {0,0,0,0,0,0,0,0};
#pragma unroll
      for (int kc = 0; kc < 9; ++kc) {
        uint32_t b[4];
        ldmx4(b[0], b[1], b[2], b[3], su32(sW1 + (cb * 16 + b4_row) * 152 + kc * 16 + b4_kof));
        mma16816(aI,     hA[kc], b[0], b[1]);
        mma16816(aI + 4, hA[kc], b[2], b[3]);
        ldmx4(b[0], b[1], b[2], b[3], su32(sW1 + (128 + cb * 16 + b4_row) * 152 + kc * 16 + b4_kof));
        mma16816(aG,     hA[kc], b[0], b[1]);
        mma16816(aG + 4, hA[kc], b[2], b[3]);
        ldmx4(b[0], b[1], b[2], b[3], su32(sW1 + (256 + cb * 16 + b4_row) * 152 + kc * 16 + b4_kof));
        mma16816(aO,     hA[kc], b[0], b[1]);
        mma16816(aO + 4, hA[kc], b[2], b[3]);
      }
      float h0 = lstm_h(aI[0], aG[0], aO[0]);
      float h1 = lstm_h(aI[1], aG[1], aO[1]);
      float h2 = lstm_h(aI[2], aG[2], aO[2]);
      float h3 = lstm_h(aI[3], aG[3], aO[3]);
      float h4 = lstm_h(aI[4], aG[4], aO[4]);
      float h5 = lstm_h(aI[5], aG[5], aO[5]);
      float h6 = lstm_h(aI[6], aG[6], aO[6]);
      float h7 = lstm_h(aI[7], aG[7], aO[7]);
      h1A[cb][0] = pack2(h0, h1);  h1A[cb][1] = pack2(h2, h3);
      h1A[cb][2] = pack2(h4, h5);  h1A[cb][3] = pack2(h6, h7);
    }
    h1A[8][0] = CA[0]; h1A[8][1] = CA[1]; h1A[8][2] = CA[2]; h1A[8][3] = CA[3];

    // ================= heads: 16x24 = h1 @ [Wp;Wv]^T (+bias chunk) =================
    float p0[8] = {0,0,0,0,0,0,0,0};   // cols 0..15 (policy)
    float p2[4] = {0,0,0,0};           // cols 16..23 (value at col 16)
#pragma unroll
    for (int kc = 0; kc < 9; ++kc) {
      uint32_t b[4];
      ldmx4(b[0], b[1], b[2], b[3], su32(sWh + b4_row * 144 + kc * 16 + b4_kof));
      mma16816(p0,     h1A[kc], b[0], b[1]);
      mma16816(p0 + 4, h1A[kc], b[2], b[3]);
      uint32_t c0, c1;
      ldmx2(c0, c1, su32(sWh + (16 + (lane & 7)) * 144 + kc * 16 + ((lane >> 3) & 1) * 8));
      mma16816(p2, h1A[kc], c0, c1);
    }

    // ---- write out ----
    const int m  = chunk * 16;
    const int rA = m + g, rB = m + g + 8;
    *(float2*)(out + (size_t)rA * 16 + 2 * q)     = make_float2(p0[0], p0[1]);
    *(float2*)(out + (size_t)rB * 16 + 2 * q)     = make_float2(p0[2], p0[3]);
    *(float2*)(out + (size_t)rA * 16 + 8 + 2 * q) = make_float2(p0[4], p0[5]);
    *(float2*)(out + (size_t)rB * 16 + 8 + 2 * q) = make_float2(p0[6], p0[7]);
    if (q == 0) { out[VOFF + rA] = p2[0]; out[VOFF + rB] = p2[2]; }
  }
}

// ---------------- launch ----------------
extern "C" void kernel_launch(void* const* d_in, const int* in_sizes, int n_in,
                              void* d_out, int out_size) {
  const float* x    = (const float*)d_in[0];
  const float* Wih0 = (const float*)d_in[1];
  // d_in[2] = Whh0 : unused (h_init = 0)
  const float* bih0 = (const float*)d_in[3];
  const float* bhh0 = (const float*)d_in[4];
  const float* Wih1 = (const float*)d_in[5];
  // d_in[6] = Whh1 : unused
  const float* bih1 = (const float*)d_in[7];
  const float* bhh1 = (const float*)d_in[8];
  const float* Wp   = (const float*)d_in[9];
  const float* bp   = (const float*)d_in[10];
  const float* Wv   = (const float*)d_in[11];
  const float* bv   = (const float*)d_in[12];
  float* out = (float*)d_out;

  cudaFuncSetAttribute(lstm_main, cudaFuncAttributeMaxDynamicSharedMemorySize, SMEM_BYTES);

  const int prep_total = 384 * 88 + 384 * 152 + 24 * 144;   // 95616
  prep_kernel<<<(prep_total + 255) / 256, 256>>>(Wih0, bih0, bhh0, Wih1, bih1, bhh1, Wp, bp, Wv, bv);
  lstm_main<<<GRID, THREADS, SMEM_BYTES>>>(x, out);
}